// round 2
// baseline (speedup 1.0000x reference)
#include <cuda_runtime.h>
#include <cuda_bf16.h>
#include <cstdint>
#include <cstddef>

// ============================================================================
// SparseBlockSeries: 4 x [subm_conv -> BN -> leaky -> subm_conv -> BN -> +res -> leaky]
// N=131072 rows, C=64 channels, K=9 neighbors, fp32.
// ============================================================================

#define CC   64
#define KK   9
#define TM   128
#define NMAX 131072
#define NCTA (NMAX / TM)
#define LEAK 0.33f

// Dynamic smem layout: W (9*64*64 f) | A double buffer (2*128*64 f) | idx (128*9 i) | ss (128*9 i)
#define SMEM_BYTES ((KK*CC*CC + 2*TM*CC) * 4 + (TM*KK) * 4 * 2)

__device__ float g_T[(size_t)NMAX * CC];
__device__ float g_Y[(size_t)NMAX * CC];
__device__ float g_X[(size_t)NMAX * CC];
__device__ float g_part[(size_t)NCTA * 128];
__device__ float g_scale[CC];
__device__ float g_shift[CC];
__device__ int   g_mask_mode;   // 0 = uint8, 1 = int32, 2 = float32

// ---- f32x2 packed math helpers (sm_103a) -----------------------------------
#define FMA2(d, a, b) \
    asm("fma.rn.f32x2 %0, %1, %2, %0;" : "+l"(d) : "l"(a), "l"(b))

__device__ __forceinline__ unsigned long long pack2(float v) {
    unsigned long long d;
    unsigned u = __float_as_uint(v);
    asm("mov.b64 %0, {%1, %1};" : "=l"(d) : "r"(u));
    return d;
}
__device__ __forceinline__ void unpack2(unsigned long long v, float& lo, float& hi) {
    unsigned a, b;
    asm("mov.b64 {%0, %1}, %2;" : "=r"(a), "=r"(b) : "l"(v));
    lo = __uint_as_float(a);
    hi = __uint_as_float(b);
}
__device__ __forceinline__ void cpa16(unsigned dst, const void* src, int src_size) {
    asm volatile("cp.async.cg.shared.global [%0], [%1], 16, %2;"
                 :: "r"(dst), "l"(src), "r"(src_size) : "memory");
}

// ---- mask dtype detection ---------------------------------------------------
__global__ void detect_kernel(const unsigned* __restrict__ m) {
    if (threadIdx.x == 0 && blockIdx.x == 0) {
        int f32ok = 1;
        unsigned upper = 0;
        for (int i = 0; i < 256; i++) {
            unsigned w = m[i];
            if (w != 0u && w != 0x3F800000u) f32ok = 0;
            upper |= (w & 0xFFFFFF00u);
        }
        g_mask_mode = f32ok ? 2 : (upper ? 0 : 1);
    }
}

// ---- fused gather-GEMM conv + BN partial stats ------------------------------
__global__ void __launch_bounds__(256) conv_kernel(
    const float* __restrict__ in, const float* __restrict__ w,
    const int* __restrict__ nidx, const void* __restrict__ nmask,
    float* __restrict__ out, float* __restrict__ partials)
{
    extern __shared__ float smem[];
    float* Wp    = smem;                      // permuted weights
    float* A     = smem + KK * CC * CC;       // double-buffered gathered rows
    int*   idx_s = (int*)(A + 2 * TM * CC);
    int*   ss_s  = idx_s + TM * KK;

    const int tid   = threadIdx.x;
    const int tile0 = blockIdx.x * TM;

    // preload neighbor idx + mask (as cp.async src-size 16 or 0)
    if (tid < TM) {
        const int mode = g_mask_mode;
        const long base = (long)(tile0 + tid) * KK;
        #pragma unroll
        for (int k = 0; k < KK; k++) {
            idx_s[tid * KK + k] = nidx[base + k];
            int mv;
            if (mode == 0)      mv = ((const unsigned char*)nmask)[base + k];
            else if (mode == 1) mv = ((const int*)nmask)[base + k] != 0;
            else                mv = ((const float*)nmask)[base + k] != 0.0f;
            ss_s[tid * KK + k] = mv ? 16 : 0;
        }
    }
    // preload W, chunk-permuted: 16B chunk q=d>>2 stored so thread cg's two
    // chunks (q=2cg, 2cg+1) land at positions cg and 8+cg -> both LDS.128
    // sweeps tile banks 0..31 exactly (conflict-free).
    for (int lin = tid; lin < KK * CC * (CC / 4); lin += 256) {
        const int kc = lin >> 4;       // k*64 + c
        const int d  = (lin & 15) << 2;
        const int off = ((d >> 2) & 1) * 32 + (d >> 3) * 4;
        float4 v = *(const float4*)(w + (size_t)kc * CC + d);
        *(float4*)(Wp + (size_t)kc * CC + off) = v;
    }
    __syncthreads();

    const int cg  = tid & 7;    // outputs cg*8 .. cg*8+7
    const int rg  = tid >> 3;   // rows rg*4 .. rg*4+3
    const int swz = (rg & 3) << 3;

    const int sr = tid >> 1, sh = tid & 1;   // staging: 2 threads per row
    const unsigned A_u = (unsigned)__cvta_generic_to_shared(A);
    const int s2 = ((sr >> 2) & 3) << 3;

    unsigned long long acc[4][4];
    #pragma unroll
    for (int i = 0; i < 4; i++)
        #pragma unroll
        for (int j = 0; j < 4; j++) acc[i][j] = 0ull;

    // prologue stage slice 0 into buf 0
    {
        const int id = idx_s[sr * KK + 0];
        const int ss = ss_s[sr * KK + 0];
        const float* src = in + (size_t)id * CC + sh * 32;
        const unsigned dbase = A_u + (unsigned)((sr * CC) * 4);
        #pragma unroll
        for (int j = 0; j < 8; j++) {
            const int c = sh * 32 + j * 4;
            cpa16(dbase + (unsigned)(((c ^ s2) << 2)), src + j * 4, ss);
        }
        asm volatile("cp.async.commit_group;" ::: "memory");
    }

    for (int k = 0; k < KK; k++) {
        const int buf = k & 1;
        if (k + 1 < KK) {
            const int id = idx_s[sr * KK + (k + 1)];
            const int ss = ss_s[sr * KK + (k + 1)];
            const float* src = in + (size_t)id * CC + sh * 32;
            const unsigned dbase = A_u + (unsigned)((((buf ^ 1) * TM + sr) * CC) * 4);
            #pragma unroll
            for (int j = 0; j < 8; j++) {
                const int c = sh * 32 + j * 4;
                cpa16(dbase + (unsigned)(((c ^ s2) << 2)), src + j * 4, ss);
            }
            asm volatile("cp.async.commit_group;" ::: "memory");
            asm volatile("cp.async.wait_group 1;" ::: "memory");
        } else {
            asm volatile("cp.async.wait_group 0;" ::: "memory");
        }
        __syncthreads();

        const float* Ab  = A + buf * TM * CC;
        const float* a0p = Ab + (rg * 4 + 0) * CC;
        const float* a1p = Ab + (rg * 4 + 1) * CC;
        const float* a2p = Ab + (rg * 4 + 2) * CC;
        const float* a3p = Ab + (rg * 4 + 3) * CC;
        const float* wk  = Wp + k * CC * CC + cg * 4;

        #pragma unroll
        for (int c4 = 0; c4 < CC; c4 += 4) {
            const int cb = c4 ^ swz;
            const float4 A0 = *(const float4*)(a0p + cb);
            const float4 A1 = *(const float4*)(a1p + cb);
            const float4 A2 = *(const float4*)(a2p + cb);
            const float4 A3 = *(const float4*)(a3p + cb);
            const float* f0 = (const float*)&A0;
            const float* f1 = (const float*)&A1;
            const float* f2 = (const float*)&A2;
            const float* f3 = (const float*)&A3;
            #pragma unroll
            for (int u = 0; u < 4; u++) {
                const int c = c4 + u;
                const ulonglong2 bl = *(const ulonglong2*)(wk + c * CC);
                const ulonglong2 bh = *(const ulonglong2*)(wk + c * CC + 32);
                const unsigned long long p0 = pack2(f0[u]);
                const unsigned long long p1 = pack2(f1[u]);
                const unsigned long long p2 = pack2(f2[u]);
                const unsigned long long p3 = pack2(f3[u]);
                FMA2(acc[0][0], p0, bl.x); FMA2(acc[0][1], p0, bl.y);
                FMA2(acc[0][2], p0, bh.x); FMA2(acc[0][3], p0, bh.y);
                FMA2(acc[1][0], p1, bl.x); FMA2(acc[1][1], p1, bl.y);
                FMA2(acc[1][2], p1, bh.x); FMA2(acc[1][3], p1, bh.y);
                FMA2(acc[2][0], p2, bl.x); FMA2(acc[2][1], p2, bl.y);
                FMA2(acc[2][2], p2, bh.x); FMA2(acc[2][3], p2, bh.y);
                FMA2(acc[3][0], p3, bl.x); FMA2(acc[3][1], p3, bl.y);
                FMA2(acc[3][2], p3, bh.x); FMA2(acc[3][3], p3, bh.y);
            }
        }
        __syncthreads();
    }

    // epilogue: write y + deterministic per-CTA partial sum/sumsq
    float* Ps = A;            // 32*64 floats
    float* Qs = A + 2048;     // 32*64 floats

    float s[8], q[8];
    #pragma unroll
    for (int j = 0; j < 8; j++) { s[j] = 0.0f; q[j] = 0.0f; }

    #pragma unroll
    for (int i = 0; i < 4; i++) {
        float y[8];
        unpack2(acc[i][0], y[0], y[1]);
        unpack2(acc[i][1], y[2], y[3]);
        unpack2(acc[i][2], y[4], y[5]);
        unpack2(acc[i][3], y[6], y[7]);
        const int m = tile0 + rg * 4 + i;
        *(float4*)(out + (size_t)m * CC + cg * 8)     = make_float4(y[0], y[1], y[2], y[3]);
        *(float4*)(out + (size_t)m * CC + cg * 8 + 4) = make_float4(y[4], y[5], y[6], y[7]);
        #pragma unroll
        for (int j = 0; j < 8; j++) { s[j] += y[j]; q[j] += y[j] * y[j]; }
    }
    #pragma unroll
    for (int j = 0; j < 8; j++) {
        Ps[rg * CC + cg * 8 + j] = s[j];
        Qs[rg * CC + cg * 8 + j] = q[j];
    }
    __syncthreads();
    if (tid < 128) {
        const float* src = (tid < 64) ? Ps : Qs;
        const int d = tid & 63;
        float a = 0.0f;
        #pragma unroll
        for (int r = 0; r < 32; r++) a += src[r * CC + d];
        partials[(size_t)blockIdx.x * 128 + tid] = a;
    }
}

// ---- BN stats reduce -> scale/shift (deterministic) -------------------------
__global__ void __launch_bounds__(512) reduce_kernel(
    const float* __restrict__ partials, int nct,
    const float* __restrict__ gamma, const float* __restrict__ beta, float invN)
{
    __shared__ float red[512];
    const int tid = threadIdx.x;
    const int c = tid & 63, which = (tid >> 6) & 1, part = tid >> 7;  // part 0..3
    float a = 0.0f;
    for (int cta = part; cta < nct; cta += 4)
        a += partials[(size_t)cta * 128 + which * 64 + c];
    red[tid] = a;
    __syncthreads();
    if (tid < 128) {
        red[tid] = red[tid] + red[tid + 128] + red[tid + 256] + red[tid + 384];
    }
    __syncthreads();
    if (tid < 64) {
        const float sum = red[tid];
        const float sq  = red[tid + 64];
        const float mean = sum * invN;
        const float var  = sq * invN - mean * mean;
        const float sc = gamma[tid] * rsqrtf(var + 1e-5f);
        g_scale[tid] = sc;
        g_shift[tid] = beta[tid] - mean * sc;
    }
}

// ---- elementwise: t = leaky(t*scale + shift) -------------------------------
__global__ void __launch_bounds__(256) bnleaky_kernel(float* __restrict__ t, int n4)
{
    const int i = blockIdx.x * blockDim.x + threadIdx.x;
    if (i >= n4) return;
    const int c = (i << 2) & 63;
    const float4 sc = *(const float4*)(g_scale + c);
    const float4 sh = *(const float4*)(g_shift + c);
    float4 v = ((const float4*)t)[i];
    float x;
    x = v.x * sc.x + sh.x; v.x = x > 0.0f ? x : LEAK * x;
    x = v.y * sc.y + sh.y; v.y = x > 0.0f ? x : LEAK * x;
    x = v.z * sc.z + sh.z; v.z = x > 0.0f ? x : LEAK * x;
    x = v.w * sc.w + sh.w; v.w = x > 0.0f ? x : LEAK * x;
    ((float4*)t)[i] = v;
}

// ---- elementwise: out = leaky(y*scale + shift + res) -----------------------
__global__ void __launch_bounds__(256) bnresleaky_kernel(
    const float* __restrict__ y, const float* __restrict__ res,
    float* __restrict__ outp, int n4)
{
    const int i = blockIdx.x * blockDim.x + threadIdx.x;
    if (i >= n4) return;
    const int c = (i << 2) & 63;
    const float4 sc = *(const float4*)(g_scale + c);
    const float4 sh = *(const float4*)(g_shift + c);
    float4 v = ((const float4*)y)[i];
    const float4 r = ((const float4*)res)[i];
    float x;
    x = v.x * sc.x + sh.x + r.x; v.x = x > 0.0f ? x : LEAK * x;
    x = v.y * sc.y + sh.y + r.y; v.y = x > 0.0f ? x : LEAK * x;
    x = v.z * sc.z + sh.z + r.z; v.z = x > 0.0f ? x : LEAK * x;
    x = v.w * sc.w + sh.w + r.w; v.w = x > 0.0f ? x : LEAK * x;
    ((float4*)outp)[i] = v;
}

// ============================================================================
extern "C" void kernel_launch(void* const* d_in, const int* in_sizes, int n_in,
                              void* d_out, int out_size)
{
    const float* features = (const float*)d_in[0];
    const int*   nidx     = (const int*)d_in[1];
    const void*  nmask    = d_in[2];
    const float* conv1w   = (const float*)d_in[3];
    const float* bn1g     = (const float*)d_in[4];
    const float* bn1b     = (const float*)d_in[5];
    const float* conv2w   = (const float*)d_in[6];
    const float* bn2g     = (const float*)d_in[7];
    const float* bn2b     = (const float*)d_in[8];
    float* out = (float*)d_out;

    const int N   = in_sizes[0] / CC;      // 131072
    const int nct = N / TM;                // 1024
    const int n4  = (N * CC) / 4;
    const float invN = 1.0f / (float)N;
    const int B = in_sizes[3] / (KK * CC * CC);  // 4 blocks

    float *pT, *pY, *pX, *pPart;
    cudaGetSymbolAddress((void**)&pT, g_T);
    cudaGetSymbolAddress((void**)&pY, g_Y);
    cudaGetSymbolAddress((void**)&pX, g_X);
    cudaGetSymbolAddress((void**)&pPart, g_part);

    cudaFuncSetAttribute(conv_kernel,
                         cudaFuncAttributeMaxDynamicSharedMemorySize, SMEM_BYTES);

    detect_kernel<<<1, 1>>>((const unsigned*)nmask);

    const float* xcur = features;
    for (int b = 0; b < B; b++) {
        const float* w1 = conv1w + (size_t)b * KK * CC * CC;
        const float* w2 = conv2w + (size_t)b * KK * CC * CC;

        conv_kernel<<<nct, 256, SMEM_BYTES>>>(xcur, w1, nidx, nmask, pT, pPart);
        reduce_kernel<<<1, 512>>>(pPart, nct, bn1g + b * CC, bn1b + b * CC, invN);
        bnleaky_kernel<<<(n4 + 255) / 256, 256>>>(pT, n4);

        conv_kernel<<<nct, 256, SMEM_BYTES>>>(pT, w2, nidx, nmask, pY, pPart);
        reduce_kernel<<<1, 512>>>(pPart, nct, bn2g + b * CC, bn2b + b * CC, invN);

        float* dst = (b == B - 1) ? out : pX;
        bnresleaky_kernel<<<(n4 + 255) / 256, 256>>>(pY, xcur, dst, n4);
        xcur = dst;
    }
}